// round 1
// baseline (speedup 1.0000x reference)
#include <cuda_runtime.h>
#include <math.h>

// ---------------------------------------------------------------------------
// LearningNMS — decomposed implementation
//   G=512 boxes, D=64, H=128, NB=2, P=136, FH=128
//   out = sigmoid(MLP(relational blocks(f)))  -> 512 floats
// ---------------------------------------------------------------------------

namespace {
constexpr int G   = 512;
constexpr int H   = 128;
constexpr int DP1 = 65;     // D+1
constexpr int P   = 136;
constexpr int FH  = 128;
constexpr int JT  = 32;     // j-tile in main kernel
constexpr float EPS    = 1e-3f;
constexpr float IOU_T  = 0.3f;
constexpr float INV_N  = 1.0f / (512.0f * 512.0f);
constexpr float INV_G  = 1.0f / 512.0f;
}

// -------------------- scratch (device globals; no allocs) -------------------
__device__ float g_bp[G * 12];        // per-box: x,y,x2,y2,cx,cy,area,lw,lh,la,1/w,1/h
__device__ float g_f[G * DP1];        // current f (scores|feats, then block outputs)
__device__ float g_gpart[G * 12];     // per-i geom partial sums/sumsq
__device__ float g_geomstat[12];      // mean[6], var[6]
__device__ float g_fstat[2 * DP1];    // mean[65], var[65]
__device__ float g_W0g[6 * H];        // BN0-scaled geom rows of W0
__device__ float g_cb[H];             // b0 + shift0 @ W0
__device__ float g_u[G * H];          // u'[i] = f[i]@W0s_fi + cb
__device__ float g_v[G * H];          // v[j]  = f[j]@W0s_fj
__device__ float g_sums[G * H];       // per-i column sums of h2
__device__ float g_sumsq[G * H];
__device__ float g_maxv[G * H];       // per-i masked column max of h2
__device__ float g_minv[G * H];       // per-i masked column min of h2
__device__ float g_bn1[2 * H];        // scale1[128], shift1[128]

// -------------------- geometry helpers --------------------------------------
struct BoxI { float x, y, x2, y2, cx, cy, ar, lw, lh, la, rw, rh; };

__device__ __forceinline__ BoxI loadbox(int i) {
    const float* bp = &g_bp[i * 12];
    BoxI b;
    b.x = bp[0];  b.y = bp[1];  b.x2 = bp[2]; b.y2 = bp[3];
    b.cx = bp[4]; b.cy = bp[5]; b.ar = bp[6];
    b.lw = bp[7]; b.lh = bp[8]; b.la = bp[9];
    b.rw = bp[10]; b.rh = bp[11];
    return b;
}

__device__ __forceinline__ void geom6(const BoxI& a, const BoxI& b, float* g) {
    float ix1 = fmaxf(a.x,  b.x),  iy1 = fmaxf(a.y,  b.y);
    float ix2 = fminf(a.x2, b.x2), iy2 = fminf(a.y2, b.y2);
    float inter = fmaxf(ix2 - ix1, 0.0f) * fmaxf(iy2 - iy1, 0.0f);
    g[0] = inter / (a.ar + b.ar - inter + 1e-6f);   // iou
    g[1] = (a.cx - b.cx) * a.rw;                    // dx
    g[2] = (a.cy - b.cy) * a.rh;                    // dy
    g[3] = b.lw - a.lw;                             // lw
    g[4] = b.lh - a.lh;                             // lh
    g[5] = b.la - a.la;                             // la
}

// -------------------- small kernels ------------------------------------------
__global__ void k_boxprep(const float* __restrict__ boxes,
                          const float* __restrict__ scores,
                          const float* __restrict__ feats) {
    int i = threadIdx.x;
    if (i < G) {
        float x = boxes[i*4+0], y = boxes[i*4+1], w = boxes[i*4+2], h = boxes[i*4+3];
        float* bp = &g_bp[i * 12];
        bp[0] = x;          bp[1] = y;
        bp[2] = x + w;      bp[3] = y + h;
        bp[4] = x + 0.5f*w; bp[5] = y + 0.5f*h;
        bp[6] = w * h;
        bp[7] = logf(w);    bp[8] = logf(h);  bp[9] = logf(w * h);
        bp[10] = 1.0f / w;  bp[11] = 1.0f / h;
        g_f[i * DP1] = scores[i];
        for (int d = 0; d < 64; d++) g_f[i * DP1 + 1 + d] = feats[i * 64 + d];
    }
}

__global__ void k_geomstats() {
    __shared__ float red[12 * 256];
    int i = blockIdx.x, tid = threadIdx.x;
    BoxI bi = loadbox(i);
    float ls[6] = {0,0,0,0,0,0}, lq[6] = {0,0,0,0,0,0};
    for (int j = tid; j < G; j += 256) {
        BoxI bj = loadbox(j);
        float g[6]; geom6(bi, bj, g);
        #pragma unroll
        for (int m = 0; m < 6; m++) { ls[m] += g[m]; lq[m] += g[m]*g[m]; }
    }
    #pragma unroll
    for (int m = 0; m < 6; m++) { red[m*256 + tid] = ls[m]; red[(6+m)*256 + tid] = lq[m]; }
    __syncthreads();
    for (int s = 128; s > 0; s >>= 1) {
        if (tid < s) {
            #pragma unroll
            for (int m = 0; m < 12; m++) red[m*256 + tid] += red[m*256 + tid + s];
        }
        __syncthreads();
    }
    if (tid == 0) {
        #pragma unroll
        for (int m = 0; m < 12; m++) g_gpart[i*12 + m] = red[m*256];
    }
}

__global__ void k_geomred() {
    int t = threadIdx.x;
    if (t < 6) {
        float S = 0.0f, Q = 0.0f;
        for (int i = 0; i < G; i++) { S += g_gpart[i*12 + t]; Q += g_gpart[i*12 + 6 + t]; }
        float mean = S * INV_N;
        float var  = fmaxf(Q * INV_N - mean*mean, 0.0f);
        g_geomstat[t] = mean; g_geomstat[6 + t] = var;
    }
}

__global__ void k_fstats() {
    int t = threadIdx.x;
    if (t < DP1) {
        float s = 0.0f, q = 0.0f;
        for (int i = 0; i < G; i++) { float v = g_f[i*DP1 + t]; s += v; q += v*v; }
        float mean = s * INV_G;
        float var  = fmaxf(q * INV_G - mean*mean, 0.0f);
        g_fstat[t] = mean; g_fstat[DP1 + t] = var;
    }
}

// fold BN0 into W0: store scaled geom rows + constant bias cb
__global__ void k_prepw(const float* __restrict__ W0k, const float* __restrict__ b0k,
                        const float* __restrict__ g0k, const float* __restrict__ bb0k) {
    int c = threadIdx.x;            // 0..127
    float cb = b0k[c];
    for (int r = 0; r < P; r++) {
        float m, vv;
        if (r < 6)       { m = g_geomstat[r];        vv = g_geomstat[6 + r]; }
        else             { int d = (r < 71) ? r - 6 : r - 71;
                           m = g_fstat[d];           vv = g_fstat[DP1 + d]; }
        float s0 = g0k[r] * rsqrtf(vv + EPS);
        float sh = bb0k[r] - m * s0;
        float wv = W0k[r * H + c];
        cb += sh * wv;
        if (r < 6) g_W0g[r * H + c] = s0 * wv;
    }
    g_cb[c] = cb;
}

// u'[i] = cb + f_i @ (scale_fi ⊙ W0[6:71]);  v[i] = f_i @ (scale_fj ⊙ W0[71:136])
__global__ void k_uv(const float* __restrict__ W0k, const float* __restrict__ g0k) {
    __shared__ float fi[DP1], sA[DP1], sB[DP1];
    int i = blockIdx.x, c = threadIdx.x;
    if (c < DP1) {
        fi[c] = g_f[i * DP1 + c];
        float rs = rsqrtf(g_fstat[DP1 + c] + EPS);
        sA[c] = g0k[6 + c]  * rs;
        sB[c] = g0k[71 + c] * rs;
    }
    __syncthreads();
    float u = g_cb[c], v = 0.0f;
    for (int d = 0; d < DP1; d++) {
        float fd = fi[d];
        u = fmaf(fd * sA[d], W0k[(6  + d) * H + c], u);
        v = fmaf(fd * sB[d], W0k[(71 + d) * H + c], v);
    }
    g_u[i * H + c] = u;
    g_v[i * H + c] = v;
}

// -------------------- main pair kernel ---------------------------------------
// One CTA per i. For each 32-j tile: geom -> h1 = relu(geom@W0g + u'+v) ->
// h2 = relu(h1 @ W1 + b1) (8j x 4c register micro-tile) -> accumulate
// column sum/sumsq (all j) and masked max/min (iou>0.3).
__global__ void __launch_bounds__(128) k_main(const float* __restrict__ W1k,
                                              const float* __restrict__ b1k) {
    extern __shared__ float sm[];
    float* W1s = sm;                 // 128*128
    float* h1s = W1s + H * H;        // JT*128 (reused as reduction scratch)
    float* gsm = h1s + JT * H;       // JT*8: geom[6], mask, pad

    int i = blockIdx.x, tid = threadIdx.x;
    int tj = tid >> 5;               // warp id 0..3 -> 8 j-rows each
    int tc = tid & 31;               // 4 columns: tc*4..tc*4+3

    for (int idx = tid; idx < H * H; idx += 128) W1s[idx] = W1k[idx];

    // per-thread column (c = tid) constants for h1 phase
    float w0c[6];
    #pragma unroll
    for (int m = 0; m < 6; m++) w0c[m] = g_W0g[m * H + tid];
    float uc = g_u[i * H + tid];

    float b1r[4];
    #pragma unroll
    for (int q = 0; q < 4; q++) b1r[q] = b1k[tc * 4 + q];

    BoxI bi = loadbox(i);

    float accS[4] = {0,0,0,0}, accQ[4] = {0,0,0,0};
    float accM[4] = {-INFINITY,-INFINITY,-INFINITY,-INFINITY};
    float accN[4] = { INFINITY, INFINITY, INFINITY, INFINITY};

    __syncthreads();

    for (int j0 = 0; j0 < G; j0 += JT) {
        // phase 0: geometry for this tile (one warp)
        if (tid < JT) {
            BoxI bj = loadbox(j0 + tid);
            float g[6]; geom6(bi, bj, g);
            #pragma unroll
            for (int m = 0; m < 6; m++) gsm[tid*8 + m] = g[m];
            gsm[tid*8 + 6] = (g[0] > IOU_T) ? 1.0f : 0.0f;
        }
        __syncthreads();

        // phase 1: h1 (thread owns column tid for all 32 jj)
        #pragma unroll 8
        for (int jj = 0; jj < JT; jj++) {
            float a = uc + g_v[(j0 + jj) * H + tid];
            const float* gp = &gsm[jj * 8];
            #pragma unroll
            for (int m = 0; m < 6; m++) a = fmaf(gp[m], w0c[m], a);
            h1s[jj * H + tid] = fmaxf(a, 0.0f);
        }
        __syncthreads();

        // phase 2: 32x128 = h1(32x128) @ W1(128x128), 8j x 4c per thread
        float acc[8][4];
        #pragma unroll
        for (int r = 0; r < 8; r++)
            #pragma unroll
            for (int q = 0; q < 4; q++) acc[r][q] = 0.0f;

        const float* hrow = &h1s[(tj * 8) * H];
        #pragma unroll 4
        for (int kk = 0; kk < H; kk += 4) {
            float4 w0 = *(const float4*)&W1s[(kk+0) * H + tc*4];
            float4 w1 = *(const float4*)&W1s[(kk+1) * H + tc*4];
            float4 w2 = *(const float4*)&W1s[(kk+2) * H + tc*4];
            float4 w3 = *(const float4*)&W1s[(kk+3) * H + tc*4];
            #pragma unroll
            for (int r = 0; r < 8; r++) {
                float4 a = *(const float4*)&hrow[r * H + kk];
                acc[r][0] = fmaf(a.x, w0.x, acc[r][0]);
                acc[r][0] = fmaf(a.y, w1.x, acc[r][0]);
                acc[r][0] = fmaf(a.z, w2.x, acc[r][0]);
                acc[r][0] = fmaf(a.w, w3.x, acc[r][0]);
                acc[r][1] = fmaf(a.x, w0.y, acc[r][1]);
                acc[r][1] = fmaf(a.y, w1.y, acc[r][1]);
                acc[r][1] = fmaf(a.z, w2.y, acc[r][1]);
                acc[r][1] = fmaf(a.w, w3.y, acc[r][1]);
                acc[r][2] = fmaf(a.x, w0.z, acc[r][2]);
                acc[r][2] = fmaf(a.y, w1.z, acc[r][2]);
                acc[r][2] = fmaf(a.z, w2.z, acc[r][2]);
                acc[r][2] = fmaf(a.w, w3.z, acc[r][2]);
                acc[r][3] = fmaf(a.x, w0.w, acc[r][3]);
                acc[r][3] = fmaf(a.y, w1.w, acc[r][3]);
                acc[r][3] = fmaf(a.z, w2.w, acc[r][3]);
                acc[r][3] = fmaf(a.w, w3.w, acc[r][3]);
            }
        }

        // phase 3: bias + relu + stats
        #pragma unroll
        for (int r = 0; r < 8; r++) {
            float msk = gsm[(tj * 8 + r) * 8 + 6];
            #pragma unroll
            for (int q = 0; q < 4; q++) {
                float hv = fmaxf(acc[r][q] + b1r[q], 0.0f);
                accS[q] += hv;
                accQ[q] = fmaf(hv, hv, accQ[q]);
                if (msk > 0.5f) {
                    accM[q] = fmaxf(accM[q], hv);
                    accN[q] = fminf(accN[q], hv);
                }
            }
        }
        __syncthreads();   // protect gsm/h1s for next tile
    }

    // cross-warp (tj) reduction, fixed order — deterministic
    float* rS = h1s;
    float* rQ = h1s + 512;
    float* rM = h1s + 1024;
    float* rN = h1s + 1536;
    int cbase = tc * 4;
    #pragma unroll
    for (int q = 0; q < 4; q++) {
        rS[tj * 128 + cbase + q] = accS[q];
        rQ[tj * 128 + cbase + q] = accQ[q];
        rM[tj * 128 + cbase + q] = accM[q];
        rN[tj * 128 + cbase + q] = accN[q];
    }
    __syncthreads();
    if (tj == 0) {
        #pragma unroll
        for (int q = 0; q < 4; q++) {
            int c = cbase + q;
            float s = 0.0f, qq = 0.0f, mx = -INFINITY, mn = INFINITY;
            #pragma unroll
            for (int t = 0; t < 4; t++) {
                s  += rS[t * 128 + c];
                qq += rQ[t * 128 + c];
                mx = fmaxf(mx, rM[t * 128 + c]);
                mn = fminf(mn, rN[t * 128 + c]);
            }
            g_sums[i * H + c] = s;   g_sumsq[i * H + c] = qq;
            g_maxv[i * H + c] = mx;  g_minv[i * H + c]  = mn;
        }
    }
}

// -------------------- BN1 finalize + pooled @ Wout ---------------------------
__global__ void k_bn1red(const float* __restrict__ g1k, const float* __restrict__ b1nk) {
    int c = threadIdx.x;
    float s = 0.0f, q = 0.0f;
    for (int i = 0; i < G; i++) { s += g_sums[i * H + c]; q += g_sumsq[i * H + c]; }
    float mean = s * INV_N;
    float var  = fmaxf(q * INV_N - mean * mean, 0.0f);
    float sc = g1k[c] * rsqrtf(var + EPS);
    g_bn1[c]     = sc;
    g_bn1[H + c] = b1nk[c] - mean * sc;
}

__global__ void k_fout(const float* __restrict__ Woutk, const float* __restrict__ boutk) {
    __shared__ float p[H];
    int i = blockIdx.x, t = threadIdx.x;
    float sc = g_bn1[t];
    // max pool commutes with monotone affine; min handles sc<0
    p[t] = ((sc >= 0.0f) ? sc * g_maxv[i * H + t] : sc * g_minv[i * H + t]) + g_bn1[H + t];
    __syncthreads();
    if (t < DP1) {
        float acc = boutk[t];
        for (int c = 0; c < H; c++) acc = fmaf(p[c], Woutk[c * DP1 + t], acc);
        g_f[i * DP1 + t] = acc;
    }
}

// -------------------- final MLP ----------------------------------------------
__global__ void k_final(const float* __restrict__ Wf0, const float* __restrict__ bf0,
                        const float* __restrict__ Wf1, const float* __restrict__ bf1,
                        const float* __restrict__ Wsc, const float* __restrict__ bsc,
                        float* __restrict__ out) {
    __shared__ float fr[DP1], y1[FH], rb[FH];
    int i = blockIdx.x, t = threadIdx.x;
    if (t < DP1) fr[t] = g_f[i * DP1 + t];
    __syncthreads();
    float a = bf0[t];
    for (int d = 0; d < DP1; d++) a = fmaf(fr[d], Wf0[d * FH + t], a);
    __syncthreads();
    y1[t] = fmaxf(a, 0.0f);
    __syncthreads();
    float b = bf1[t];
    for (int d = 0; d < FH; d++) b = fmaf(y1[d], Wf1[d * FH + t], b);
    float y2 = fmaxf(b, 0.0f);
    rb[t] = y2 * Wsc[t];
    __syncthreads();
    for (int s = 64; s > 0; s >>= 1) {
        if (t < s) rb[t] += rb[t + s];
        __syncthreads();
    }
    if (t == 0) out[i] = 1.0f / (1.0f + expf(-(rb[0] + bsc[0])));
}

// -------------------- launch -------------------------------------------------
extern "C" void kernel_launch(void* const* d_in, const int* in_sizes, int n_in,
                              void* d_out, int out_size) {
    const float* boxes  = (const float*)d_in[0];
    const float* scores = (const float*)d_in[1];
    const float* feats  = (const float*)d_in[2];
    const float* bn0_g  = (const float*)d_in[3];
    const float* bn0_b  = (const float*)d_in[4];
    const float* W0     = (const float*)d_in[5];
    const float* b0     = (const float*)d_in[6];
    const float* W1     = (const float*)d_in[7];
    const float* b1     = (const float*)d_in[8];
    const float* bn1_g  = (const float*)d_in[9];
    const float* bn1_b  = (const float*)d_in[10];
    const float* Wout   = (const float*)d_in[11];
    const float* bout   = (const float*)d_in[12];
    const float* Wf0    = (const float*)d_in[13];
    const float* bf0    = (const float*)d_in[14];
    const float* Wf1    = (const float*)d_in[15];
    const float* bf1    = (const float*)d_in[16];
    const float* Wsc    = (const float*)d_in[17];
    const float* bsc    = (const float*)d_in[18];
    float* out = (float*)d_out;

    const size_t mainsmem = (size_t)(H * H + JT * H + JT * 8) * sizeof(float); // ~83KB
    cudaFuncSetAttribute(k_main, cudaFuncAttributeMaxDynamicSharedMemorySize,
                         (int)mainsmem);

    k_boxprep<<<1, 512>>>(boxes, scores, feats);
    k_geomstats<<<512, 256>>>();
    k_geomred<<<1, 32>>>();

    for (int k = 0; k < 2; k++) {
        const float* W0k   = W0 + (size_t)k * P * H;
        const float* b0k   = b0 + k * H;
        const float* g0k   = bn0_g + k * P;
        const float* bb0k  = bn0_b + k * P;
        const float* W1k   = W1 + (size_t)k * H * H;
        const float* b1k   = b1 + k * H;
        const float* g1k   = bn1_g + k * H;
        const float* b1nk  = bn1_b + k * H;
        const float* Woutk = Wout + (size_t)k * H * DP1;
        const float* boutk = bout + k * DP1;

        k_fstats<<<1, 128>>>();
        k_prepw<<<1, 128>>>(W0k, b0k, g0k, bb0k);
        k_uv<<<512, 128>>>(W0k, g0k);
        k_main<<<512, 128, mainsmem>>>(W1k, b1k);
        k_bn1red<<<1, 128>>>(g1k, b1nk);
        k_fout<<<512, 128>>>(Woutk, boutk);
    }

    k_final<<<512, 128>>>(Wf0, bf0, Wf1, bf1, Wsc, bsc, out);
}

// round 3
// speedup vs baseline: 1.8495x; 1.8495x over previous
#include <cuda_runtime.h>
#include <math.h>
#include <stdint.h>

// ---------------------------------------------------------------------------
// LearningNMS — decomposed, tensor-core (tf32 mma.sync) implementation
//   G=512 boxes, D=64, H=128, NB=2, P=136, FH=128
// ---------------------------------------------------------------------------

namespace {
constexpr int G   = 512;
constexpr int H   = 128;
constexpr int DP1 = 65;     // D+1
constexpr int P   = 136;
constexpr int FH  = 128;
constexpr int JT  = 32;     // j-tile in main kernel
constexpr int SW  = 132;    // padded smem stride (conflict-free frag loads)
constexpr float EPS    = 1e-3f;
constexpr float IOU_T  = 0.3f;
constexpr float INV_N  = 1.0f / (512.0f * 512.0f);
constexpr float INV_G  = 1.0f / 512.0f;
}

// -------------------- scratch (device globals; no allocs) -------------------
__device__ float g_bp[G * 12];
__device__ float g_f[G * DP1];
__device__ float g_gpart[G * 12];
__device__ float g_geomstat[12];
__device__ float g_fstat[2 * DP1];
__device__ float g_W0g[6 * H];
__device__ float g_cb[H];
__device__ float g_u[G * H];
__device__ float g_v[G * H];
__device__ float g_sums[G * H];
__device__ float g_sumsq[G * H];
__device__ float g_maxv[G * H];
__device__ float g_minv[G * H];
__device__ float g_bn1[2 * H];

// -------------------- helpers ------------------------------------------------
struct BoxI { float x, y, x2, y2, cx, cy, ar, lw, lh, la, rw, rh; };

__device__ __forceinline__ BoxI loadbox(int i) {
    const float* bp = &g_bp[i * 12];
    BoxI b;
    b.x = bp[0];  b.y = bp[1];  b.x2 = bp[2]; b.y2 = bp[3];
    b.cx = bp[4]; b.cy = bp[5]; b.ar = bp[6];
    b.lw = bp[7]; b.lh = bp[8]; b.la = bp[9];
    b.rw = bp[10]; b.rh = bp[11];
    return b;
}

__device__ __forceinline__ void geom6(const BoxI& a, const BoxI& b, float* g) {
    float ix1 = fmaxf(a.x,  b.x),  iy1 = fmaxf(a.y,  b.y);
    float ix2 = fminf(a.x2, b.x2), iy2 = fminf(a.y2, b.y2);
    float inter = fmaxf(ix2 - ix1, 0.0f) * fmaxf(iy2 - iy1, 0.0f);
    g[0] = inter / (a.ar + b.ar - inter + 1e-6f);
    g[1] = (a.cx - b.cx) * a.rw;
    g[2] = (a.cy - b.cy) * a.rh;
    g[3] = b.lw - a.lw;
    g[4] = b.lh - a.lh;
    g[5] = b.la - a.la;
}

__device__ __forceinline__ uint32_t f2tf32(float x) {
    uint32_t r;
    asm("cvt.rna.tf32.f32 %0, %1;" : "=r"(r) : "f"(x));
    return r;
}

__device__ __forceinline__ void mma_tf32(float* c, const uint32_t* a, const uint32_t* b) {
    asm volatile(
        "mma.sync.aligned.m16n8k8.row.col.f32.tf32.tf32.f32 "
        "{%0,%1,%2,%3}, {%4,%5,%6,%7}, {%8,%9}, {%0,%1,%2,%3};"
        : "+f"(c[0]), "+f"(c[1]), "+f"(c[2]), "+f"(c[3])
        : "r"(a[0]), "r"(a[1]), "r"(a[2]), "r"(a[3]), "r"(b[0]), "r"(b[1]));
}

// -------------------- small kernels ------------------------------------------
__global__ void k_boxprep(const float* __restrict__ boxes,
                          const float* __restrict__ scores,
                          const float* __restrict__ feats) {
    int i = threadIdx.x;
    if (i < G) {
        float x = boxes[i*4+0], y = boxes[i*4+1], w = boxes[i*4+2], h = boxes[i*4+3];
        float* bp = &g_bp[i * 12];
        bp[0] = x;          bp[1] = y;
        bp[2] = x + w;      bp[3] = y + h;
        bp[4] = x + 0.5f*w; bp[5] = y + 0.5f*h;
        bp[6] = w * h;
        bp[7] = logf(w);    bp[8] = logf(h);  bp[9] = logf(w * h);
        bp[10] = 1.0f / w;  bp[11] = 1.0f / h;
        g_f[i * DP1] = scores[i];
        for (int d = 0; d < 64; d++) g_f[i * DP1 + 1 + d] = feats[i * 64 + d];
    }
}

__global__ void k_geomstats() {
    __shared__ float red[12 * 256];
    int i = blockIdx.x, tid = threadIdx.x;
    BoxI bi = loadbox(i);
    float ls[6] = {0,0,0,0,0,0}, lq[6] = {0,0,0,0,0,0};
    for (int j = tid; j < G; j += 256) {
        BoxI bj = loadbox(j);
        float g[6]; geom6(bi, bj, g);
        #pragma unroll
        for (int m = 0; m < 6; m++) { ls[m] += g[m]; lq[m] += g[m]*g[m]; }
    }
    #pragma unroll
    for (int m = 0; m < 6; m++) { red[m*256 + tid] = ls[m]; red[(6+m)*256 + tid] = lq[m]; }
    __syncthreads();
    for (int s = 128; s > 0; s >>= 1) {
        if (tid < s) {
            #pragma unroll
            for (int m = 0; m < 12; m++) red[m*256 + tid] += red[m*256 + tid + s];
        }
        __syncthreads();
    }
    if (tid == 0) {
        #pragma unroll
        for (int m = 0; m < 12; m++) g_gpart[i*12 + m] = red[m*256];
    }
}

// 12 warps, one per stat column; shfl reduce over 512 rows
__global__ void k_geomred() {
    __shared__ float ws[12];
    int l = threadIdx.x, m = threadIdx.y;
    float s = 0.0f;
    for (int i = l; i < G; i += 32) s += g_gpart[i * 12 + m];
    #pragma unroll
    for (int d = 16; d > 0; d >>= 1) s += __shfl_xor_sync(0xffffffffu, s, d);
    if (l == 0) ws[m] = s;
    __syncthreads();
    if (m == 0 && l < 6) {
        float mean = ws[l] * INV_N;
        float var  = fmaxf(ws[6 + l] * INV_N - mean * mean, 0.0f);
        g_geomstat[l] = mean; g_geomstat[6 + l] = var;
    }
}

// 544 threads: 8 row-chunks per column
__global__ void k_fstats() {
    __shared__ float2 red[520];
    int t = threadIdx.x;
    if (t < 520) {
        int col = t >> 3, sub = t & 7;
        float s = 0.0f, q = 0.0f;
        for (int r = sub * 64; r < sub * 64 + 64; r++) {
            float v = g_f[r * DP1 + col];
            s += v; q = fmaf(v, v, q);
        }
        red[t] = make_float2(s, q);
    }
    __syncthreads();
    if (t < 520 && (t & 7) == 0) {
        float s = 0.0f, q = 0.0f;
        #pragma unroll
        for (int k = 0; k < 8; k++) { s += red[t + k].x; q += red[t + k].y; }
        int col = t >> 3;
        float mean = s * INV_G;
        float var  = fmaxf(q * INV_G - mean * mean, 0.0f);
        g_fstat[col] = mean; g_fstat[DP1 + col] = var;
    }
}

// fold BN0 into W0: 128 cols x 8 row-chunks
__global__ void k_prepw(const float* __restrict__ W0k, const float* __restrict__ b0k,
                        const float* __restrict__ g0k, const float* __restrict__ bb0k) {
    __shared__ float part[8][128];
    int c = threadIdx.x, yy = threadIdx.y;
    float cb = 0.0f;
    int r0 = yy * 17, r1 = min(r0 + 17, P);
    for (int r = r0; r < r1; r++) {
        float m, vv;
        if (r < 6) { m = g_geomstat[r]; vv = g_geomstat[6 + r]; }
        else       { int d = (r < 71) ? r - 6 : r - 71;
                     m = g_fstat[d];   vv = g_fstat[DP1 + d]; }
        float s0 = g0k[r] * rsqrtf(vv + EPS);
        float sh = bb0k[r] - m * s0;
        float wv = W0k[r * H + c];
        cb += sh * wv;
        if (r < 6) g_W0g[r * H + c] = s0 * wv;
    }
    part[yy][c] = cb;
    __syncthreads();
    if (yy == 0) {
        float t = b0k[c];
        #pragma unroll
        for (int k = 0; k < 8; k++) t += part[k][c];
        g_cb[c] = t;
    }
}

__global__ void k_uv(const float* __restrict__ W0k, const float* __restrict__ g0k) {
    __shared__ float fi[DP1], sA[DP1], sB[DP1];
    int i = blockIdx.x, c = threadIdx.x;
    if (c < DP1) {
        fi[c] = g_f[i * DP1 + c];
        float rs = rsqrtf(g_fstat[DP1 + c] + EPS);
        sA[c] = g0k[6 + c]  * rs;
        sB[c] = g0k[71 + c] * rs;
    }
    __syncthreads();
    float u = g_cb[c], v = 0.0f;
    for (int d = 0; d < DP1; d++) {
        float fd = fi[d];
        u = fmaf(fd * sA[d], W0k[(6  + d) * H + c], u);
        v = fmaf(fd * sB[d], W0k[(71 + d) * H + c], v);
    }
    g_u[i * H + c] = u;
    g_v[i * H + c] = v;
}

// -------------------- main pair kernel (tf32 mma) ----------------------------
// One CTA per i, 128 threads. Per 32-j tile:
//   phase0: geom+mask (warp0)  phase1: h1 = relu(geom@W0g + u + v) -> tf32 smem
//   phase2: h2 = h1(32x128) @ W1(128x128) via m16n8k8 tf32 mma (warp owns 32 n-cols)
//   phase3: bias+relu+stats in C-fragment layout (per-thread col accumulators)
__global__ void __launch_bounds__(128) k_main(const float* __restrict__ W1k,
                                              const float* __restrict__ b1k) {
    extern __shared__ uint32_t smu[];
    uint32_t* W1s = smu;                    // [128][SW] transposed: W1s[n*SW+k]
    uint32_t* h1s = smu + H * SW;           // [32][SW]: h1s[j*SW+c]
    float*    gsm = (float*)(smu + H * SW + JT * SW);  // [32][8]

    int i = blockIdx.x, tid = threadIdx.x;
    int lane = tid & 31, wrp = tid >> 5;
    int gid = lane >> 2, tig = lane & 3;
    int nbase = wrp * 32;

    // W1 -> smem transposed + tf32
    for (int idx = tid; idx < H * H; idx += 128) {
        int k = idx >> 7, n = idx & 127;
        W1s[n * SW + k] = f2tf32(W1k[idx]);
    }

    float w0c[6];
    #pragma unroll
    for (int m = 0; m < 6; m++) w0c[m] = g_W0g[m * H + tid];
    float uc = g_u[i * H + tid];

    float bias[4][2];
    #pragma unroll
    for (int ni = 0; ni < 4; ni++)
        #pragma unroll
        for (int q = 0; q < 2; q++)
            bias[ni][q] = b1k[nbase + ni * 8 + 2 * tig + q];

    BoxI bi = loadbox(i);

    float S[4][2], Qa[4][2], Mx[4][2], Mn[4][2];
    #pragma unroll
    for (int ni = 0; ni < 4; ni++)
        #pragma unroll
        for (int q = 0; q < 2; q++) {
            S[ni][q] = 0.0f; Qa[ni][q] = 0.0f;
            Mx[ni][q] = -INFINITY; Mn[ni][q] = INFINITY;
        }

    __syncthreads();

    for (int j0 = 0; j0 < G; j0 += JT) {
        // phase 0: geometry for tile (warp 0)
        if (tid < JT) {
            BoxI bj = loadbox(j0 + tid);
            float g[6]; geom6(bi, bj, g);
            #pragma unroll
            for (int m = 0; m < 6; m++) gsm[tid * 8 + m] = g[m];
            gsm[tid * 8 + 6] = (g[0] > IOU_T) ? 1.0f : 0.0f;
        }
        __syncthreads();

        // phase 1: h1 column tid for all 32 j
        #pragma unroll 8
        for (int jj = 0; jj < JT; jj++) {
            float a = uc + g_v[(j0 + jj) * H + tid];
            const float* gp = &gsm[jj * 8];
            #pragma unroll
            for (int m = 0; m < 6; m++) a = fmaf(gp[m], w0c[m], a);
            h1s[jj * SW + tid] = f2tf32(fmaxf(a, 0.0f));
        }
        __syncthreads();

        // phase 2: tf32 mma, warp covers m=32, n=[nbase, nbase+32), k=128
        float acc[2][4][4];
        #pragma unroll
        for (int mi = 0; mi < 2; mi++)
            #pragma unroll
            for (int ni = 0; ni < 4; ni++)
                #pragma unroll
                for (int q = 0; q < 4; q++) acc[mi][ni][q] = 0.0f;

        #pragma unroll 4
        for (int ki = 0; ki < 16; ki++) {
            int kb = ki * 8;
            uint32_t a[2][4], b[4][2];
            #pragma unroll
            for (int mi = 0; mi < 2; mi++) {
                int r0 = mi * 16 + gid;
                a[mi][0] = h1s[r0 * SW + kb + tig];
                a[mi][1] = h1s[(r0 + 8) * SW + kb + tig];
                a[mi][2] = h1s[r0 * SW + kb + tig + 4];
                a[mi][3] = h1s[(r0 + 8) * SW + kb + tig + 4];
            }
            #pragma unroll
            for (int ni = 0; ni < 4; ni++) {
                int col = nbase + ni * 8 + gid;
                b[ni][0] = W1s[col * SW + kb + tig];
                b[ni][1] = W1s[col * SW + kb + tig + 4];
            }
            #pragma unroll
            for (int mi = 0; mi < 2; mi++)
                #pragma unroll
                for (int ni = 0; ni < 4; ni++)
                    mma_tf32(acc[mi][ni], a[mi], b[ni]);
        }

        // phase 3: bias + relu + stats (C-fragment layout)
        #pragma unroll
        for (int mi = 0; mi < 2; mi++) {
            float m0 = gsm[(mi * 16 + gid) * 8 + 6];
            float m1 = gsm[(mi * 16 + gid + 8) * 8 + 6];
            #pragma unroll
            for (int ni = 0; ni < 4; ni++) {
                #pragma unroll
                for (int q = 0; q < 2; q++) {
                    float h0 = fmaxf(acc[mi][ni][q]     + bias[ni][q], 0.0f);
                    float h1 = fmaxf(acc[mi][ni][q + 2] + bias[ni][q], 0.0f);
                    S[ni][q] += h0 + h1;
                    Qa[ni][q] = fmaf(h0, h0, Qa[ni][q]);
                    Qa[ni][q] = fmaf(h1, h1, Qa[ni][q]);
                    if (m0 > 0.5f) { Mx[ni][q] = fmaxf(Mx[ni][q], h0); Mn[ni][q] = fminf(Mn[ni][q], h0); }
                    if (m1 > 0.5f) { Mx[ni][q] = fmaxf(Mx[ni][q], h1); Mn[ni][q] = fminf(Mn[ni][q], h1); }
                }
            }
        }
        __syncthreads();   // protect gsm/h1s for next tile
    }

    // reduce across the 8 lanes sharing each column (lanes tig + 4m)
    #pragma unroll
    for (int ni = 0; ni < 4; ni++)
        #pragma unroll
        for (int q = 0; q < 2; q++) {
            #pragma unroll
            for (int d = 4; d <= 16; d <<= 1) {
                S[ni][q]  += __shfl_xor_sync(0xffffffffu, S[ni][q],  d);
                Qa[ni][q] += __shfl_xor_sync(0xffffffffu, Qa[ni][q], d);
                Mx[ni][q] = fmaxf(Mx[ni][q], __shfl_xor_sync(0xffffffffu, Mx[ni][q], d));
                Mn[ni][q] = fminf(Mn[ni][q], __shfl_xor_sync(0xffffffffu, Mn[ni][q], d));
            }
        }
    if (gid == 0) {   // lanes 0..3 (tig == lane)
        #pragma unroll
        for (int ni = 0; ni < 4; ni++)
            #pragma unroll
            for (int q = 0; q < 2; q++) {
                int c = nbase + ni * 8 + 2 * tig + q;
                g_sums[i * H + c]  = S[ni][q];
                g_sumsq[i * H + c] = Qa[ni][q];
                g_maxv[i * H + c]  = Mx[ni][q];
                g_minv[i * H + c]  = Mn[ni][q];
            }
    }
}

// -------------------- BN1 finalize + pooled @ Wout ---------------------------
__global__ void k_bn1red(const float* __restrict__ g1k, const float* __restrict__ b1nk) {
    __shared__ float ps[8][128], pq[8][128];
    int c = threadIdx.x, yy = threadIdx.y;
    float s = 0.0f, q = 0.0f;
    for (int i = yy * 64; i < yy * 64 + 64; i++) {
        s += g_sums[i * H + c];
        q += g_sumsq[i * H + c];
    }
    ps[yy][c] = s; pq[yy][c] = q;
    __syncthreads();
    if (yy == 0) {
        #pragma unroll
        for (int k = 1; k < 8; k++) { s += ps[k][c]; q += pq[k][c]; }
        float mean = s * INV_N;
        float var  = fmaxf(q * INV_N - mean * mean, 0.0f);
        float sc = g1k[c] * rsqrtf(var + EPS);
        g_bn1[c]     = sc;
        g_bn1[H + c] = b1nk[c] - mean * sc;
    }
}

__global__ void k_fout(const float* __restrict__ Woutk, const float* __restrict__ boutk) {
    __shared__ float p[H];
    int i = blockIdx.x, t = threadIdx.x;
    float sc = g_bn1[t];
    p[t] = ((sc >= 0.0f) ? sc * g_maxv[i * H + t] : sc * g_minv[i * H + t]) + g_bn1[H + t];
    __syncthreads();
    if (t < DP1) {
        float acc = boutk[t];
        for (int c = 0; c < H; c++) acc = fmaf(p[c], Woutk[c * DP1 + t], acc);
        g_f[i * DP1 + t] = acc;
    }
}

// -------------------- final MLP ----------------------------------------------
__global__ void k_final(const float* __restrict__ Wf0, const float* __restrict__ bf0,
                        const float* __restrict__ Wf1, const float* __restrict__ bf1,
                        const float* __restrict__ Wsc, const float* __restrict__ bsc,
                        float* __restrict__ out) {
    __shared__ float fr[DP1], y1[FH], rb[FH];
    int i = blockIdx.x, t = threadIdx.x;
    if (t < DP1) fr[t] = g_f[i * DP1 + t];
    __syncthreads();
    float a = bf0[t];
    for (int d = 0; d < DP1; d++) a = fmaf(fr[d], Wf0[d * FH + t], a);
    __syncthreads();
    y1[t] = fmaxf(a, 0.0f);
    __syncthreads();
    float b = bf1[t];
    for (int d = 0; d < FH; d++) b = fmaf(y1[d], Wf1[d * FH + t], b);
    float y2 = fmaxf(b, 0.0f);
    rb[t] = y2 * Wsc[t];
    __syncthreads();
    for (int s = 64; s > 0; s >>= 1) {
        if (t < s) rb[t] += rb[t + s];
        __syncthreads();
    }
    if (t == 0) out[i] = 1.0f / (1.0f + expf(-(rb[0] + bsc[0])));
}

// -------------------- launch -------------------------------------------------
extern "C" void kernel_launch(void* const* d_in, const int* in_sizes, int n_in,
                              void* d_out, int out_size) {
    const float* boxes  = (const float*)d_in[0];
    const float* scores = (const float*)d_in[1];
    const float* feats  = (const float*)d_in[2];
    const float* bn0_g  = (const float*)d_in[3];
    const float* bn0_b  = (const float*)d_in[4];
    const float* W0     = (const float*)d_in[5];
    const float* b0     = (const float*)d_in[6];
    const float* W1     = (const float*)d_in[7];
    const float* b1     = (const float*)d_in[8];
    const float* bn1_g  = (const float*)d_in[9];
    const float* bn1_b  = (const float*)d_in[10];
    const float* Wout   = (const float*)d_in[11];
    const float* bout   = (const float*)d_in[12];
    const float* Wf0    = (const float*)d_in[13];
    const float* bf0    = (const float*)d_in[14];
    const float* Wf1    = (const float*)d_in[15];
    const float* bf1    = (const float*)d_in[16];
    const float* Wsc    = (const float*)d_in[17];
    const float* bsc    = (const float*)d_in[18];
    float* out = (float*)d_out;

    const size_t mainsmem = (size_t)(H * SW + JT * SW + JT * 8) * sizeof(uint32_t); // ~85.5KB
    cudaFuncSetAttribute(k_main, cudaFuncAttributeMaxDynamicSharedMemorySize,
                         (int)mainsmem);

    k_boxprep<<<1, 512>>>(boxes, scores, feats);
    k_geomstats<<<512, 256>>>();
    k_geomred<<<1, dim3(32, 12)>>>();

    for (int k = 0; k < 2; k++) {
        const float* W0k   = W0 + (size_t)k * P * H;
        const float* b0k   = b0 + k * H;
        const float* g0k   = bn0_g + k * P;
        const float* bb0k  = bn0_b + k * P;
        const float* W1k   = W1 + (size_t)k * H * H;
        const float* b1k   = b1 + k * H;
        const float* g1k   = bn1_g + k * H;
        const float* b1nk  = bn1_b + k * H;
        const float* Woutk = Wout + (size_t)k * H * DP1;
        const float* boutk = bout + k * DP1;

        k_fstats<<<1, 544>>>();
        k_prepw<<<1, dim3(128, 8)>>>(W0k, b0k, g0k, bb0k);
        k_uv<<<512, 128>>>(W0k, g0k);
        k_main<<<512, 128, mainsmem>>>(W1k, b1k);
        k_bn1red<<<1, dim3(128, 8)>>>(g1k, b1nk);
        k_fout<<<512, 128>>>(Woutk, boutk);
    }

    k_final<<<512, 128>>>(Wf0, bf0, Wf1, bf1, Wsc, bsc, out);
}

// round 5
// speedup vs baseline: 3.1946x; 1.7273x over previous
#include <cuda_runtime.h>
#include <cuda_bf16.h>
#include <math.h>
#include <stdint.h>

// ---------------------------------------------------------------------------
// LearningNMS — decomposed, bf16 mma.sync (m16n8k16) implementation
//   G=512, D=64, H=128, NB=2, P=136, FH=128
// ---------------------------------------------------------------------------

namespace {
constexpr int G   = 512;
constexpr int H   = 128;
constexpr int DP1 = 65;
constexpr int P   = 136;
constexpr int FH  = 128;
constexpr int JT  = 32;     // j rows per tile
constexpr int SWP = 68;     // uint32 (bf16x2) stride: (4*gid+tig)%32 permutes banks
constexpr float EPS    = 1e-3f;
constexpr float IOU_T  = 0.3f;
constexpr float INV_N  = 1.0f / (512.0f * 512.0f);
constexpr float INV_G  = 1.0f / 512.0f;
}

// -------------------- scratch (device globals; no allocs) -------------------
__device__ float g_bp[G * 12];
__device__ float g_f[G * DP1];
__device__ float g_gpart[G * 12];
__device__ float g_geomstat[12];
__device__ float g_fstat[2 * DP1];
__device__ float g_W0g[6 * H];
__device__ float g_cb[H];
__device__ float g_u[G * H];
__device__ float g_v[G * H];
__device__ float g_sums[G * H];
__device__ float g_sumsq[G * H];
__device__ float g_maxv[G * H];
__device__ float g_minv[G * H];
__device__ float g_bn1[2 * H];

// -------------------- helpers ------------------------------------------------
struct BoxI { float x, y, x2, y2, cx, cy, ar, lw, lh, la, rw, rh; };

__device__ __forceinline__ BoxI loadbox(int i) {
    const float* bp = &g_bp[i * 12];
    BoxI b;
    b.x = bp[0];  b.y = bp[1];  b.x2 = bp[2]; b.y2 = bp[3];
    b.cx = bp[4]; b.cy = bp[5]; b.ar = bp[6];
    b.lw = bp[7]; b.lh = bp[8]; b.la = bp[9];
    b.rw = bp[10]; b.rh = bp[11];
    return b;
}

__device__ __forceinline__ void geom6(const BoxI& a, const BoxI& b, float* g) {
    float ix1 = fmaxf(a.x,  b.x),  iy1 = fmaxf(a.y,  b.y);
    float ix2 = fminf(a.x2, b.x2), iy2 = fminf(a.y2, b.y2);
    float inter = fmaxf(ix2 - ix1, 0.0f) * fmaxf(iy2 - iy1, 0.0f);
    g[0] = inter / (a.ar + b.ar - inter + 1e-6f);
    g[1] = (a.cx - b.cx) * a.rw;
    g[2] = (a.cy - b.cy) * a.rh;
    g[3] = b.lw - a.lw;
    g[4] = b.lh - a.lh;
    g[5] = b.la - a.la;
}

__device__ __forceinline__ void mma_bf16(float* c, const uint32_t* a, const uint32_t* b) {
    asm volatile(
        "mma.sync.aligned.m16n8k16.row.col.f32.bf16.bf16.f32 "
        "{%0,%1,%2,%3}, {%4,%5,%6,%7}, {%8,%9}, {%0,%1,%2,%3};"
        : "+f"(c[0]), "+f"(c[1]), "+f"(c[2]), "+f"(c[3])
        : "r"(a[0]), "r"(a[1]), "r"(a[2]), "r"(a[3]), "r"(b[0]), "r"(b[1]));
}

__device__ __forceinline__ uint32_t packbf2(float lo, float hi) {
    __nv_bfloat162 v = __floats2bfloat162_rn(lo, hi);
    return *(uint32_t*)&v;
}

// -------------------- small kernels ------------------------------------------
__global__ void k_boxprep(const float* __restrict__ boxes,
                          const float* __restrict__ scores,
                          const float* __restrict__ feats) {
    int i = threadIdx.x;
    if (i < G) {
        float x = boxes[i*4+0], y = boxes[i*4+1], w = boxes[i*4+2], h = boxes[i*4+3];
        float* bp = &g_bp[i * 12];
        bp[0] = x;          bp[1] = y;
        bp[2] = x + w;      bp[3] = y + h;
        bp[4] = x + 0.5f*w; bp[5] = y + 0.5f*h;
        bp[6] = w * h;
        bp[7] = logf(w);    bp[8] = logf(h);  bp[9] = logf(w * h);
        bp[10] = 1.0f / w;  bp[11] = 1.0f / h;
        g_f[i * DP1] = scores[i];
        for (int d = 0; d < 64; d++) g_f[i * DP1 + 1 + d] = feats[i * 64 + d];
    }
}

__global__ void k_geomstats() {
    __shared__ float red[12 * 256];
    int i = blockIdx.x, tid = threadIdx.x;
    BoxI bi = loadbox(i);
    float ls[6] = {0,0,0,0,0,0}, lq[6] = {0,0,0,0,0,0};
    for (int j = tid; j < G; j += 256) {
        BoxI bj = loadbox(j);
        float g[6]; geom6(bi, bj, g);
        #pragma unroll
        for (int m = 0; m < 6; m++) { ls[m] += g[m]; lq[m] += g[m]*g[m]; }
    }
    #pragma unroll
    for (int m = 0; m < 6; m++) { red[m*256 + tid] = ls[m]; red[(6+m)*256 + tid] = lq[m]; }
    __syncthreads();
    for (int s = 128; s > 0; s >>= 1) {
        if (tid < s) {
            #pragma unroll
            for (int m = 0; m < 12; m++) red[m*256 + tid] += red[m*256 + tid + s];
        }
        __syncthreads();
    }
    if (tid == 0) {
        #pragma unroll
        for (int m = 0; m < 12; m++) g_gpart[i*12 + m] = red[m*256];
    }
}

__global__ void k_geomred() {
    __shared__ float ws[12];
    int l = threadIdx.x, m = threadIdx.y;
    float s = 0.0f;
    for (int i = l; i < G; i += 32) s += g_gpart[i * 12 + m];
    #pragma unroll
    for (int d = 16; d > 0; d >>= 1) s += __shfl_xor_sync(0xffffffffu, s, d);
    if (l == 0) ws[m] = s;
    __syncthreads();
    if (m == 0 && l < 6) {
        float mean = ws[l] * INV_N;
        float var  = fmaxf(ws[6 + l] * INV_N - mean * mean, 0.0f);
        g_geomstat[l] = mean; g_geomstat[6 + l] = var;
    }
}

// fused: f stats (mean/var over G rows) then BN0-fold into W0
__global__ void k_fstats_prepw(const float* __restrict__ W0k, const float* __restrict__ b0k,
                               const float* __restrict__ g0k, const float* __restrict__ bb0k) {
    __shared__ float2 red[520];
    __shared__ float part[8][128];
    int x = threadIdx.x, y = threadIdx.y;
    int t = y * 128 + x;

    // --- f stats ---
    if (t < 520) {
        int col = t >> 3, sub = t & 7;
        float s = 0.0f, q = 0.0f;
        for (int r = sub * 64; r < sub * 64 + 64; r++) {
            float v = g_f[r * DP1 + col];
            s += v; q = fmaf(v, v, q);
        }
        red[t] = make_float2(s, q);
    }
    __syncthreads();
    if (t < 520 && (t & 7) == 0) {
        float s = 0.0f, q = 0.0f;
        #pragma unroll
        for (int k = 0; k < 8; k++) { s += red[t + k].x; q += red[t + k].y; }
        int col = t >> 3;
        float mean = s * INV_G;
        float var  = fmaxf(q * INV_G - mean * mean, 0.0f);
        g_fstat[col] = mean; g_fstat[DP1 + col] = var;
    }
    __syncthreads();

    // --- prepw: fold BN0 into W0 ---
    int c = x, yy = y;
    float cb = 0.0f;
    int r0 = yy * 17, r1 = min(r0 + 17, P);
    for (int r = r0; r < r1; r++) {
        float m, vv;
        if (r < 6) { m = g_geomstat[r]; vv = g_geomstat[6 + r]; }
        else       { int d = (r < 71) ? r - 6 : r - 71;
                     m = g_fstat[d];   vv = g_fstat[DP1 + d]; }
        float s0 = g0k[r] * rsqrtf(vv + EPS);
        float sh = bb0k[r] - m * s0;
        float wv = W0k[r * H + c];
        cb += sh * wv;
        if (r < 6) g_W0g[r * H + c] = s0 * wv;
    }
    part[yy][c] = cb;
    __syncthreads();
    if (yy == 0) {
        float tt = b0k[c];
        #pragma unroll
        for (int k = 0; k < 8; k++) tt += part[k][c];
        g_cb[c] = tt;
    }
}

__global__ void k_uv(const float* __restrict__ W0k, const float* __restrict__ g0k) {
    __shared__ float fi[DP1], sA[DP1], sB[DP1];
    int i = blockIdx.x, c = threadIdx.x;
    if (c < DP1) {
        fi[c] = g_f[i * DP1 + c];
        float rs = rsqrtf(g_fstat[DP1 + c] + EPS);
        sA[c] = g0k[6 + c]  * rs;
        sB[c] = g0k[71 + c] * rs;
    }
    __syncthreads();
    float u = g_cb[c], v = 0.0f;
    for (int d = 0; d < DP1; d++) {
        float fd = fi[d];
        u = fmaf(fd * sA[d], W0k[(6  + d) * H + c], u);
        v = fmaf(fd * sB[d], W0k[(71 + d) * H + c], v);
    }
    g_u[i * H + c] = u;
    g_v[i * H + c] = v;
}

// -------------------- main pair kernel (bf16 m16n8k16 mma) -------------------
// One CTA per i, 128 threads, static smem 44.5KB -> 4 CTAs/SM -> single wave.
// Per 32-j tile:
//   phase0: geom+mask (warp0)
//   phase1: h1[j][c=tid] = relu(geom@W0g + u + v) -> bf16 smem (k-paired)
//   phase2: h2 = h1(32x128) @ W1(128x128): 8 k-steps of m16n8k16 bf16 mma
//   phase3: bias+relu+stats in C-fragment layout
__global__ void __launch_bounds__(128, 4) k_main(const float* __restrict__ W1k,
                                                 const float* __restrict__ b1k) {
    __shared__ uint32_t W1p[H][SWP];   // W1p[n][kk] = bf16x2 of W1[2kk..2kk+1][n]
    __shared__ uint32_t h1p[JT][SWP];  // h1p[j][kk] = bf16x2 of h1[j][2kk..2kk+1]
    __shared__ float    gsm[JT][8];

    int i = blockIdx.x, tid = threadIdx.x;
    int lane = tid & 31, wrp = tid >> 5;
    int gid = lane >> 2, tig = lane & 3;
    int nbase = wrp * 32;

    // W1 -> bf16 pairs, transposed: thread owns output column c = tid
    {
        int c = tid;
        #pragma unroll 8
        for (int kk = 0; kk < 64; kk++)
            W1p[c][kk] = packbf2(W1k[(2 * kk) * H + c], W1k[(2 * kk + 1) * H + c]);
    }

    float w0c[6];
    #pragma unroll
    for (int m = 0; m < 6; m++) w0c[m] = g_W0g[m * H + tid];
    float uc = g_u[i * H + tid];

    float bias[4][2];
    #pragma unroll
    for (int ni = 0; ni < 4; ni++)
        #pragma unroll
        for (int q = 0; q < 2; q++)
            bias[ni][q] = b1k[nbase + ni * 8 + 2 * tig + q];

    BoxI bi = loadbox(i);

    float S[4][2], Qa[4][2], Mx[4][2], Mn[4][2];
    #pragma unroll
    for (int ni = 0; ni < 4; ni++)
        #pragma unroll
        for (int q = 0; q < 2; q++) {
            S[ni][q] = 0.0f; Qa[ni][q] = 0.0f;
            Mx[ni][q] = -INFINITY; Mn[ni][q] = INFINITY;
        }

    __syncthreads();

    for (int j0 = 0; j0 < G; j0 += JT) {
        // phase 0: geometry for tile (warp 0)
        if (tid < JT) {
            BoxI bj = loadbox(j0 + tid);
            float g[6]; geom6(bi, bj, g);
            #pragma unroll
            for (int m = 0; m < 6; m++) gsm[tid][m] = g[m];
            gsm[tid][6] = (g[0] > IOU_T) ? 1.0f : 0.0f;
        }
        __syncthreads();

        // phase 1: h1 column c=tid for all 32 j (16-bit store into pair array)
        #pragma unroll 8
        for (int jj = 0; jj < JT; jj++) {
            float a = uc + g_v[(j0 + jj) * H + tid];
            const float* gp = gsm[jj];
            #pragma unroll
            for (int m = 0; m < 6; m++) a = fmaf(gp[m], w0c[m], a);
            ((__nv_bfloat16*)&h1p[jj][tid >> 1])[tid & 1] =
                __float2bfloat16(fmaxf(a, 0.0f));
        }
        __syncthreads();

        // phase 2: bf16 mma, warp covers m=32, n=[nbase,nbase+32), k=128 (8 steps)
        float acc[2][4][4];
        #pragma unroll
        for (int mi = 0; mi < 2; mi++)
            #pragma unroll
            for (int ni = 0; ni < 4; ni++)
                #pragma unroll
                for (int q = 0; q < 4; q++) acc[mi][ni][q] = 0.0f;

        #pragma unroll
        for (int ki = 0; ki < 8; ki++) {
            int kb = ki * 8;   // pair index base (K=16 per step)
            uint32_t a[2][4], b[4][2];
            #pragma unroll
            for (int mi = 0; mi < 2; mi++) {
                int r0 = mi * 16 + gid;
                a[mi][0] = h1p[r0][kb + tig];
                a[mi][1] = h1p[r0 + 8][kb + tig];
                a[mi][2] = h1p[r0][kb + tig + 4];
                a[mi][3] = h1p[r0 + 8][kb + tig + 4];
            }
            #pragma unroll
            for (int ni = 0; ni < 4; ni++) {
                int col = nbase + ni * 8 + gid;
                b[ni][0] = W1p[col][kb + tig];
                b[ni][1] = W1p[col][kb + tig + 4];
            }
            #pragma unroll
            for (int mi = 0; mi < 2; mi++)
                #pragma unroll
                for (int ni = 0; ni < 4; ni++)
                    mma_bf16(acc[mi][ni], a[mi], b[ni]);
        }

        // phase 3: bias + relu + stats (C-fragment layout)
        #pragma unroll
        for (int mi = 0; mi < 2; mi++) {
            float m0 = gsm[mi * 16 + gid][6];
            float m1 = gsm[mi * 16 + gid + 8][6];
            #pragma unroll
            for (int ni = 0; ni < 4; ni++) {
                #pragma unroll
                for (int q = 0; q < 2; q++) {
                    float h0 = fmaxf(acc[mi][ni][q]     + bias[ni][q], 0.0f);
                    float h1 = fmaxf(acc[mi][ni][q + 2] + bias[ni][q], 0.0f);
                    S[ni][q] += h0 + h1;
                    Qa[ni][q] = fmaf(h0, h0, Qa[ni][q]);
                    Qa[ni][q] = fmaf(h1, h1, Qa[ni][q]);
                    if (m0 > 0.5f) { Mx[ni][q] = fmaxf(Mx[ni][q], h0); Mn[ni][q] = fminf(Mn[ni][q], h0); }
                    if (m1 > 0.5f) { Mx[ni][q] = fmaxf(Mx[ni][q], h1); Mn[ni][q] = fminf(Mn[ni][q], h1); }
                }
            }
        }
        __syncthreads();   // protect gsm/h1p for next tile
    }

    // reduce across the 8 lanes sharing each column (gid axis: lanes d=4,8,16)
    #pragma unroll
    for (int ni = 0; ni < 4; ni++)
        #pragma unroll
        for (int q = 0; q < 2; q++) {
            #pragma unroll
            for (int d = 4; d <= 16; d <<= 1) {
                S[ni][q]  += __shfl_xor_sync(0xffffffffu, S[ni][q],  d);
                Qa[ni][q] += __shfl_xor_sync(0xffffffffu, Qa[ni][q], d);
                Mx[ni][q] = fmaxf(Mx[ni][q], __shfl_xor_sync(0xffffffffu, Mx[ni][q], d));
                Mn[ni][q] = fminf(Mn[ni][q], __shfl_xor_sync(0xffffffffu, Mn[ni][q], d));
            }
        }
    if (gid == 0) {
        #pragma unroll
        for (int ni = 0; ni < 4; ni++)
            #pragma unroll
            for (int q = 0; q < 2; q++) {
                int c = nbase + ni * 8 + 2 * tig + q;
                g_sums[i * H + c]  = S[ni][q];
                g_sumsq[i * H + c] = Qa[ni][q];
                g_maxv[i * H + c]  = Mx[ni][q];
                g_minv[i * H + c]  = Mn[ni][q];
            }
    }
}

// -------------------- BN1 finalize + pooled @ Wout ---------------------------
__global__ void k_bn1red(const float* __restrict__ g1k, const float* __restrict__ b1nk) {
    __shared__ float ps[8][128], pq[8][128];
    int c = threadIdx.x, yy = threadIdx.y;
    float s = 0.0f, q = 0.0f;
    for (int i = yy * 64; i < yy * 64 + 64; i++) {
        s += g_sums[i * H + c];
        q += g_sumsq[i * H + c];
    }
    ps[yy][c] = s; pq[yy][c] = q;
    __syncthreads();
    if (yy == 0) {
        #pragma unroll
        for (int k = 1; k < 8; k++) { s += ps[k][c]; q += pq[k][c]; }
        float mean = s * INV_N;
        float var  = fmaxf(q * INV_N - mean * mean, 0.0f);
        float sc = g1k[c] * rsqrtf(var + EPS);
        g_bn1[c]     = sc;
        g_bn1[H + c] = b1nk[c] - mean * sc;
    }
}

__global__ void k_fout(const float* __restrict__ Woutk, const float* __restrict__ boutk) {
    __shared__ float p[H];
    int i = blockIdx.x, t = threadIdx.x;
    float sc = g_bn1[t];
    p[t] = ((sc >= 0.0f) ? sc * g_maxv[i * H + t] : sc * g_minv[i * H + t]) + g_bn1[H + t];
    __syncthreads();
    if (t < DP1) {
        float acc = boutk[t];
        for (int c = 0; c < H; c++) acc = fmaf(p[c], Woutk[c * DP1 + t], acc);
        g_f[i * DP1 + t] = acc;
    }
}

// -------------------- final MLP ----------------------------------------------
__global__ void k_final(const float* __restrict__ Wf0, const float* __restrict__ bf0,
                        const float* __restrict__ Wf1, const float* __restrict__ bf1,
                        const float* __restrict__ Wsc, const float* __restrict__ bsc,
                        float* __restrict__ out) {
    __shared__ float fr[DP1], y1[FH], rb[FH];
    int i = blockIdx.x, t = threadIdx.x;
    if (t < DP1) fr[t] = g_f[i * DP1 + t];
    __syncthreads();
    float a = bf0[t];
    for (int d = 0; d < DP1; d++) a = fmaf(fr[d], Wf0[d * FH + t], a);
    __syncthreads();
    y1[t] = fmaxf(a, 0.0f);
    __syncthreads();
    float b = bf1[t];
    for (int d = 0; d < FH; d++) b = fmaf(y1[d], Wf1[d * FH + t], b);
    float y2 = fmaxf(b, 0.0f);
    rb[t] = y2 * Wsc[t];
    __syncthreads();
    for (int s = 64; s > 0; s >>= 1) {
        if (t < s) rb[t] += rb[t + s];
        __syncthreads();
    }
    if (t == 0) out[i] = 1.0f / (1.0f + expf(-(rb[0] + bsc[0])));
}

// -------------------- launch -------------------------------------------------
extern "C" void kernel_launch(void* const* d_in, const int* in_sizes, int n_in,
                              void* d_out, int out_size) {
    const float* boxes  = (const float*)d_in[0];
    const float* scores = (const float*)d_in[1];
    const float* feats  = (const float*)d_in[2];
    const float* bn0_g  = (const float*)d_in[3];
    const float* bn0_b  = (const float*)d_in[4];
    const float* W0     = (const float*)d_in[5];
    const float* b0     = (const float*)d_in[6];
    const float* W1     = (const float*)d_in[7];
    const float* b1     = (const float*)d_in[8];
    const float* bn1_g  = (const float*)d_in[9];
    const float* bn1_b  = (const float*)d_in[10];
    const float* Wout   = (const float*)d_in[11];
    const float* bout   = (const float*)d_in[12];
    const float* Wf0    = (const float*)d_in[13];
    const float* bf0    = (const float*)d_in[14];
    const float* Wf1    = (const float*)d_in[15];
    const float* bf1    = (const float*)d_in[16];
    const float* Wsc    = (const float*)d_in[17];
    const float* bsc    = (const float*)d_in[18];
    float* out = (float*)d_out;

    k_boxprep<<<1, 512>>>(boxes, scores, feats);
    k_geomstats<<<512, 256>>>();
    k_geomred<<<1, dim3(32, 12)>>>();

    for (int k = 0; k < 2; k++) {
        const float* W0k   = W0 + (size_t)k * P * H;
        const float* b0k   = b0 + k * H;
        const float* g0k   = bn0_g + k * P;
        const float* bb0k  = bn0_b + k * P;
        const float* W1k   = W1 + (size_t)k * H * H;
        const float* b1k   = b1 + k * H;
        const float* g1k   = bn1_g + k * H;
        const float* b1nk  = bn1_b + k * H;
        const float* Woutk = Wout + (size_t)k * H * DP1;
        const float* boutk = bout + k * DP1;

        k_fstats_prepw<<<1, dim3(128, 8)>>>(W0k, b0k, g0k, bb0k);
        k_uv<<<512, 128>>>(W0k, g0k);
        k_main<<<512, 128>>>(W1k, b1k);
        k_bn1red<<<1, dim3(128, 8)>>>(g1k, b1nk);
        k_fout<<<512, 128>>>(Woutk, boutk);
    }

    k_final<<<512, 128>>>(Wf0, bf0, Wf1, bf1, Wsc, bsc, out);
}